// round 6
// baseline (speedup 1.0000x reference)
#include <cuda_runtime.h>
#include <cuda_bf16.h>
#include <cstdint>

// ---------------------------------------------------------------------------
// SpatialLinearAttention — mma.sync split-bf16, W2 fusion, fused q-softmax
//   16-warp GEMM CTAs (2x8 warps, warp tile 64x16), 3-stage cp.async pipeline
// ---------------------------------------------------------------------------

#define NB      32
#define CDIM    256
#define NSP     4096
#define O3      768
#define NHEADS  8
#define DHEAD   32
#define XB_STRIDE (CDIM * 16 * NSP)
#define XC_STRIDE (16 * NSP)

// ---------------- scratch ---------------------------------------------------
__device__ float g_kv[(size_t)NB * 512 * NSP];           // k rows 0-255, v 256-511
__device__ uint4 g_w_hi[24576];                          // 768 x 256 bf16
__device__ uint4 g_w_lo[24576];
__device__ uint4 g_xt_hi[4194304];                       // [b][n][c] bf16
__device__ uint4 g_xt_lo[4194304];
__device__ uint4 g_qsm_hi[4194304];                      // [b][n][c] bf16
__device__ uint4 g_qsm_lo[4194304];
__device__ uint4 g_w2_hi[262144];                        // [b] 256x256 bf16
__device__ uint4 g_w2_lo[262144];
__device__ float g_ctx[NB * NHEADS * DHEAD * DHEAD];     // sum exp(k)*v
__device__ float g_ksum[NB * NHEADS * DHEAD];

// ---------------- helpers ---------------------------------------------------
__device__ __forceinline__ uint32_t smem_u32(const void* p) {
    uint32_t a;
    asm("{ .reg .u64 t; cvta.to.shared.u64 t, %1; cvt.u32.u64 %0, t; }" : "=r"(a) : "l"(p));
    return a;
}
__device__ __forceinline__ void cp16(uint32_t saddr, const void* g) {
    asm volatile("cp.async.ca.shared.global [%0], [%1], 16;" :: "r"(saddr), "l"(g) : "memory");
}
__device__ __forceinline__ void cp_commit() {
    asm volatile("cp.async.commit_group;" ::: "memory");
}
template <int N>
__device__ __forceinline__ void cp_wait() {
    asm volatile("cp.async.wait_group %0;" :: "n"(N) : "memory");
}
__device__ __forceinline__ void ldsm_x4(uint32_t* r, uint32_t addr) {
    asm volatile("ldmatrix.sync.aligned.m8n8.x4.shared.b16 {%0,%1,%2,%3}, [%4];"
                 : "=r"(r[0]), "=r"(r[1]), "=r"(r[2]), "=r"(r[3]) : "r"(addr));
}
__device__ __forceinline__ void mma16816(float* d, const uint32_t* a, const uint32_t* b) {
    asm volatile(
        "mma.sync.aligned.m16n8k16.row.col.f32.bf16.bf16.f32 "
        "{%0,%1,%2,%3}, {%4,%5,%6,%7}, {%8,%9}, {%0,%1,%2,%3};"
        : "+f"(d[0]), "+f"(d[1]), "+f"(d[2]), "+f"(d[3])
        : "r"(a[0]), "r"(a[1]), "r"(a[2]), "r"(a[3]), "r"(b[0]), "r"(b[1]));
}
__device__ __forceinline__ unsigned short bf16_bits(float v) {
    return __bfloat16_as_ushort(__float2bfloat16(v));
}

// ---------------------------------------------------------------------------
__global__ void zero_kernel()
{
    const int i = blockIdx.x * 256 + threadIdx.x;
    if (i < NB * NHEADS * DHEAD * DHEAD) g_ctx[i] = 0.f;
    if (i < NB * NHEADS * DHEAD) g_ksum[i] = 0.f;
}

__global__ void conv_w_kernel(const float* __restrict__ wq)
{
    int i = blockIdx.x * 256 + threadIdx.x;
    float v = wq[i];
    __nv_bfloat16 hi = __float2bfloat16(v);
    ((__nv_bfloat16*)g_w_hi)[i] = hi;
    ((__nv_bfloat16*)g_w_lo)[i] = __float2bfloat16(v - __bfloat162float(hi));
}

__global__ __launch_bounds__(256) void conv_x_kernel(const float* __restrict__ x)
{
    __shared__ float s[32][129];
    const int bz = blockIdx.z;
    const int bi = bz >> 4, fi = bz & 15;
    const int n0 = blockIdx.x * 128;
    const int c0 = blockIdx.y * 32;
    const float* __restrict__ X = x + (size_t)bi * XB_STRIDE + (size_t)fi * NSP;
    const int tid = threadIdx.x;
#pragma unroll
    for (int it = 0; it < 16; it++) {
        int i = tid + it * 256;
        int c = i >> 7, n = i & 127;
        s[c][n] = X[(size_t)(c0 + c) * XC_STRIDE + n0 + n];
    }
    __syncthreads();
    __nv_bfloat16* ah = (__nv_bfloat16*)g_xt_hi;
    __nv_bfloat16* al = (__nv_bfloat16*)g_xt_lo;
#pragma unroll
    for (int it = 0; it < 16; it++) {
        int i = tid + it * 256;
        int n = i >> 5, c = i & 31;
        float v = s[c][n];
        __nv_bfloat16 hi = __float2bfloat16(v);
        size_t o = ((size_t)bz * NSP + n0 + n) * CDIM + c0 + c;
        ah[o] = hi;
        al[o] = __float2bfloat16(v - __bfloat162float(hi));
    }
}

// ---------------------------------------------------------------------------
// GEMM: CTA M128 x N128, K=256 (4 chunks of 64), 512 threads = 16 warps (2x8),
// warp tile 64x16 (4x2 m16n8k16), 3-stage cp.async pipeline.
// ---------------------------------------------------------------------------
#define BUF_BYTES 73728
#define OFF_AH 0
#define OFF_AL 18432
#define OFF_BH 36864
#define OFF_BL 55296

template <int MODE>
__global__ __launch_bounds__(512, 1) void gemm_mma_kernel(float* __restrict__ out,
                                                          const float* __restrict__ bias)
{
    extern __shared__ char smem[];
    const uint32_t sbase = smem_u32(smem);
    const int tid = threadIdx.x;
    const int lane = tid & 31;
    const int wid = tid >> 5;
    const int wm = wid >> 3;          // 0..1
    const int wn = wid & 7;           // 0..7
    const int bz = blockIdx.z;
    const int m0 = blockIdx.y * 128;
    const int n0 = blockIdx.x * 128;

    const uint4* __restrict__ Ah;
    const uint4* __restrict__ Al;
    if (MODE == 0) { Ah = g_w_hi; Al = g_w_lo; }
    else { Ah = g_w2_hi + (size_t)bz * 8192; Al = g_w2_lo + (size_t)bz * 8192; }
    const uint4* __restrict__ Bh = (MODE == 0 ? g_xt_hi : g_qsm_hi) + (size_t)bz * NSP * CDIM / 8;
    const uint4* __restrict__ Bl = (MODE == 0 ? g_xt_lo : g_qsm_lo) + (size_t)bz * NSP * CDIM / 8;

    float acc[4][2][4];
#pragma unroll
    for (int i = 0; i < 4; i++)
#pragma unroll
        for (int j = 0; j < 2; j++)
#pragma unroll
            for (int k = 0; k < 4; k++) acc[i][j][k] = 0.f;

    auto issue = [&](int kc, int buf) {
        const uint32_t bo = sbase + buf * BUF_BYTES;
#pragma unroll
        for (int i = tid; i < 1024; i += 512) {
            const int r = i >> 3, c = i & 7;
            const uint32_t so = (uint32_t)(r * 144 + c * 16);
            const size_t gA = (size_t)(m0 + r) * 32 + kc * 8 + c;
            const size_t gB = (size_t)(n0 + r) * 32 + kc * 8 + c;
            cp16(bo + OFF_AH + so, Ah + gA);
            cp16(bo + OFF_AL + so, Al + gA);
            cp16(bo + OFF_BH + so, Bh + gB);
            cp16(bo + OFF_BL + so, Bl + gB);
        }
    };

    issue(0, 0); cp_commit();
    issue(1, 1); cp_commit();

    const int arow = wm * 64 + (lane & 15);
    const int acsel = (lane >> 4) << 3;
    const int brow = wn * 16 + (lane & 7) + ((lane >> 4) & 1) * 8;
    const int bcsel = ((lane >> 3) & 1) << 3;

    for (int kc = 0; kc < 4; kc++) {
        if (kc == 3) cp_wait<0>(); else cp_wait<1>();
        __syncthreads();

        const uint32_t bo = sbase + (kc % 3) * BUF_BYTES;
#pragma unroll
        for (int ks = 0; ks < 4; ks++) {
            const int k0 = ks * 16;
            uint32_t ah[4][4], al[4][4], bh[4], bl[4];
#pragma unroll
            for (int mt = 0; mt < 4; mt++) {
                const uint32_t ao = bo + (uint32_t)((arow + mt * 16) * 144 + (k0 + acsel) * 2);
                ldsm_x4(ah[mt], ao + OFF_AH);
                ldsm_x4(al[mt], ao + OFF_AL);
            }
            {
                const uint32_t bo2 = bo + (uint32_t)(brow * 144 + (k0 + bcsel) * 2);
                ldsm_x4(bh, bo2 + OFF_BH);
                ldsm_x4(bl, bo2 + OFF_BL);
            }
#pragma unroll
            for (int mt = 0; mt < 4; mt++)
#pragma unroll
                for (int nt = 0; nt < 2; nt++) {
                    mma16816(acc[mt][nt], ah[mt], bh + nt * 2);
                    mma16816(acc[mt][nt], ah[mt], bl + nt * 2);
                    mma16816(acc[mt][nt], al[mt], bh + nt * 2);
                }
        }
        __syncthreads();
        if (kc + 2 < 4) { issue(kc + 2, (kc + 2) % 3); cp_commit(); }
    }

    // ------------- epilogue -------------
    if (MODE == 0 && m0 < 256) {
        // fused q-softmax: stage 128x128 fp32 tile (stride 132), softmax over d
        float* s = (float*)smem;
#pragma unroll
        for (int mt = 0; mt < 4; mt++) {
            const int r0 = wm * 64 + mt * 16 + (lane >> 2);
            const int c = wn * 16 + (lane & 3) * 2;
#pragma unroll
            for (int nt = 0; nt < 2; nt++) {
                *(float2*)&s[(size_t)r0 * 132 + c + nt * 8] =
                    make_float2(acc[mt][nt][0], acc[mt][nt][1]);
                *(float2*)&s[(size_t)(r0 + 8) * 132 + c + nt * 8] =
                    make_float2(acc[mt][nt][2], acc[mt][nt][3]);
            }
        }
        __syncthreads();
        {
            const int h = tid >> 7;       // 0..3 local head
            const int n = tid & 127;
            float qv[32];
            float m = -3.0e38f;
#pragma unroll
            for (int d = 0; d < 32; d++) {
                qv[d] = s[(size_t)(h * 32 + d) * 132 + n];
                m = fmaxf(m, qv[d]);
            }
            float sum = 0.f;
#pragma unroll
            for (int d = 0; d < 32; d++) {
                qv[d] = __expf(qv[d] - m);
                sum += qv[d];
            }
            const float rs = 1.0f / sum;
            const size_t base = ((size_t)bz * NSP + n0 + n) * CDIM + m0 + h * 32;
            uint4* oh = g_qsm_hi + (base >> 3);
            uint4* ol = g_qsm_lo + (base >> 3);
#pragma unroll
            for (int g = 0; g < 4; g++) {
                uint32_t hw[4], lw[4];
#pragma unroll
                for (int p = 0; p < 4; p++) {
                    const float v0 = qv[g * 8 + p * 2] * rs;
                    const float v1 = qv[g * 8 + p * 2 + 1] * rs;
                    const unsigned short h0 = bf16_bits(v0);
                    const unsigned short h1 = bf16_bits(v1);
                    const float r0 = v0 - __bfloat162float(__ushort_as_bfloat16(h0));
                    const float r1 = v1 - __bfloat162float(__ushort_as_bfloat16(h1));
                    hw[p] = (uint32_t)h0 | ((uint32_t)h1 << 16);
                    lw[p] = (uint32_t)bf16_bits(r0) | ((uint32_t)bf16_bits(r1) << 16);
                }
                oh[g] = make_uint4(hw[0], hw[1], hw[2], hw[3]);
                ol[g] = make_uint4(lw[0], lw[1], lw[2], lw[3]);
            }
        }
    } else if (MODE == 0) {
        const int rbase = m0 - 256 + wm * 64 + (lane >> 2);
        const int cbase = n0 + wn * 16 + (lane & 3) * 2;
        float* __restrict__ O = g_kv + (size_t)bz * 512 * NSP;
#pragma unroll
        for (int mt = 0; mt < 4; mt++) {
#pragma unroll
            for (int nt = 0; nt < 2; nt++) {
                const int c = cbase + nt * 8;
                float* p0 = O + (size_t)(rbase + mt * 16) * NSP + c;
                float* p1 = O + (size_t)(rbase + mt * 16 + 8) * NSP + c;
                *(float2*)p0 = make_float2(acc[mt][nt][0], acc[mt][nt][1]);
                *(float2*)p1 = make_float2(acc[mt][nt][2], acc[mt][nt][3]);
            }
        }
    } else {
        const int rbase = m0 + wm * 64 + (lane >> 2);
        const int cbase = n0 + wn * 16 + (lane & 3) * 2;
        const int bi = bz >> 4, fi = bz & 15;
        float* __restrict__ O = out + (size_t)bi * XB_STRIDE + (size_t)fi * NSP;
#pragma unroll
        for (int mt = 0; mt < 4; mt++) {
            const int r0 = rbase + mt * 16;
            const float b0 = bias[r0];
            const float b1 = bias[r0 + 8];
#pragma unroll
            for (int nt = 0; nt < 2; nt++) {
                const int c = cbase + nt * 8;
                float* p0 = O + (size_t)r0 * XC_STRIDE + c;
                float* p1 = O + (size_t)(r0 + 8) * XC_STRIDE + c;
                *(float2*)p0 = make_float2(acc[mt][nt][0] + b0, acc[mt][nt][1] + b0);
                *(float2*)p1 = make_float2(acc[mt][nt][2] + b1, acc[mt][nt][3] + b1);
            }
        }
    }
}

// ---------------------------------------------------------------------------
// ctx partials + ksum: grid (16 chunks of 256 n, 256 bh). Unshifted exp(k).
// ---------------------------------------------------------------------------
__global__ __launch_bounds__(256) void ctx_kernel()
{
    __shared__ float ks[32][260];
    __shared__ float vs[32][260];
    const int bh = blockIdx.y;
    const int n0 = blockIdx.x * 256;
    const float* __restrict__ kp =
        g_kv + (size_t)(bh >> 3) * 512 * NSP + (size_t)((bh & 7) * DHEAD) * NSP;
    const float* __restrict__ vp = kp + (size_t)256 * NSP;
    const int tid = threadIdx.x;
    const int lane = tid & 31;
    const int warp = tid >> 5;

#pragma unroll
    for (int it = 0; it < 8; it++) {
        const int i = tid + it * 256;
        const int d = i >> 6, j4 = (i & 63) * 4;
        float4 kv = *(const float4*)(kp + (size_t)d * NSP + n0 + j4);
        ks[d][j4 + 0] = __expf(kv.x);
        ks[d][j4 + 1] = __expf(kv.y);
        ks[d][j4 + 2] = __expf(kv.z);
        ks[d][j4 + 3] = __expf(kv.w);
        *(float4*)&vs[d][j4] = *(const float4*)(vp + (size_t)d * NSP + n0 + j4);
    }
    __syncthreads();

    float acc[4] = {0.f, 0.f, 0.f, 0.f};
    const int w4 = warp * 4;
#pragma unroll
    for (int j = 0; j < 256; j += 4) {
        const float4 vv4 = *(const float4*)&vs[lane][j];
#pragma unroll
        for (int dd = 0; dd < 4; dd++) {
            const float4 kk4 = *(const float4*)&ks[w4 + dd][j];
            acc[dd] += kk4.x * vv4.x + kk4.y * vv4.y + kk4.z * vv4.z + kk4.w * vv4.w;
        }
    }
#pragma unroll
    for (int dd = 0; dd < 4; dd++) {
        float s = 0.f;
#pragma unroll
        for (int j = lane; j < 256; j += 32) s += ks[w4 + dd][j];
#pragma unroll
        for (int off = 16; off; off >>= 1) s += __shfl_xor_sync(0xffffffffu, s, off);
        if (lane == 0) atomicAdd(&g_ksum[bh * 32 + w4 + dd], s);
        atomicAdd(&g_ctx[bh * 1024 + (w4 + dd) * 32 + lane], acc[dd]);
    }
}

// ---------------------------------------------------------------------------
// W2[b][o][h*32+d] = scale/ksum[b,h,d] * sum_e w_out[o][h*32+e] * ctx[b,h,d,e]
// ---------------------------------------------------------------------------
__global__ __launch_bounds__(256) void w2_kernel(const float* __restrict__ w_out)
{
    __shared__ float wblk[256][33];
    __shared__ float cblk[32][33];
    __shared__ float rcp[32];
    const int b = blockIdx.x;
    const int tid = threadIdx.x;
    const float scale = 0.1767766953f;

    __nv_bfloat16* W2h = (__nv_bfloat16*)(g_w2_hi + (size_t)b * 8192);
    __nv_bfloat16* W2l = (__nv_bfloat16*)(g_w2_lo + (size_t)b * 8192);

    for (int h = 0; h < NHEADS; h++) {
#pragma unroll
        for (int i = tid; i < 8192; i += 256) {
            const int o = i >> 5, e = i & 31;
            wblk[o][e] = w_out[o * 256 + h * 32 + e];
        }
#pragma unroll
        for (int i = tid; i < 1024; i += 256)
            cblk[i >> 5][i & 31] = g_ctx[(b * 8 + h) * 1024 + i];
        if (tid < 32) rcp[tid] = scale / g_ksum[(b * 8 + h) * 32 + tid];
        __syncthreads();

        const int o = tid;
        float res[32];
#pragma unroll
        for (int d = 0; d < 32; d++) {
            float a = 0.f;
#pragma unroll
            for (int e = 0; e < 32; e++) a += wblk[o][e] * cblk[d][e];
            res[d] = a * rcp[d];
        }
#pragma unroll
        for (int d = 0; d < 32; d++) {
            const int c = h * 32 + d;
            __nv_bfloat16 hi = __float2bfloat16(res[d]);
            W2h[o * 256 + c] = hi;
            W2l[o * 256 + c] = __float2bfloat16(res[d] - __bfloat162float(hi));
        }
        __syncthreads();
    }
}

// ---------------------------------------------------------------------------
extern "C" void kernel_launch(void* const* d_in, const int* in_sizes, int n_in,
                              void* d_out, int out_size)
{
    (void)in_sizes; (void)n_in; (void)out_size;
    const float* x     = (const float*)d_in[0];
    const float* w_qkv = (const float*)d_in[1];
    const float* w_out = (const float*)d_in[2];
    const float* b_out = (const float*)d_in[3];
    float* out = (float*)d_out;

    const int SMEM = 3 * BUF_BYTES;   // 221184
    cudaFuncSetAttribute(gemm_mma_kernel<0>, cudaFuncAttributeMaxDynamicSharedMemorySize, SMEM);
    cudaFuncSetAttribute(gemm_mma_kernel<1>, cudaFuncAttributeMaxDynamicSharedMemorySize, SMEM);

    zero_kernel<<<1056, 256>>>();
    conv_w_kernel<<<768, 256>>>(w_qkv);
    conv_x_kernel<<<dim3(NSP / 128, CDIM / 32, NB), 256>>>(x);
    gemm_mma_kernel<0><<<dim3(NSP / 128, O3 / 128, NB), 512, SMEM>>>(nullptr, nullptr);
    ctx_kernel<<<dim3(16, NB * NHEADS), 256>>>();
    w2_kernel<<<NB, 256>>>(w_out);
    gemm_mma_kernel<1><<<dim3(NSP / 128, CDIM / 128, NB), 512, SMEM>>>(out, b_out);
}

// round 9
// speedup vs baseline: 1.5750x; 1.5750x over previous
#include <cuda_runtime.h>
#include <cuda_bf16.h>
#include <cstdint>

// ---------------------------------------------------------------------------
// SpatialLinearAttention — mma.sync split-bf16, W2 fusion, fused q-softmax
//   8-warp GEMM CTAs (2x4 warps, warp tile 64x32), 3-stage cp.async pipeline,
//   register-level fragment double buffering, x4 B ldmatrix.
// ---------------------------------------------------------------------------

#define NB      32
#define CDIM    256
#define NSP     4096
#define O3      768
#define NHEADS  8
#define DHEAD   32
#define XB_STRIDE (CDIM * 16 * NSP)
#define XC_STRIDE (16 * NSP)

// ---------------- scratch ---------------------------------------------------
__device__ float g_kv[(size_t)NB * 512 * NSP];           // k rows 0-255, v 256-511
__device__ uint4 g_w_hi[24576];                          // 768 x 256 bf16
__device__ uint4 g_w_lo[24576];
__device__ uint4 g_xt_hi[4194304];                       // [b][n][c] bf16
__device__ uint4 g_xt_lo[4194304];
__device__ uint4 g_qsm_hi[4194304];                      // [b][n][c] bf16
__device__ uint4 g_qsm_lo[4194304];
__device__ uint4 g_w2_hi[262144];                        // [b] 256x256 bf16
__device__ uint4 g_w2_lo[262144];
__device__ float g_ctx[NB * NHEADS * DHEAD * DHEAD];     // sum exp(k)*v
__device__ float g_ksum[NB * NHEADS * DHEAD];

// ---------------- helpers ---------------------------------------------------
__device__ __forceinline__ uint32_t smem_u32(const void* p) {
    uint32_t a;
    asm("{ .reg .u64 t; cvta.to.shared.u64 t, %1; cvt.u32.u64 %0, t; }" : "=r"(a) : "l"(p));
    return a;
}
__device__ __forceinline__ void cp16(uint32_t saddr, const void* g) {
    asm volatile("cp.async.ca.shared.global [%0], [%1], 16;" :: "r"(saddr), "l"(g) : "memory");
}
__device__ __forceinline__ void cp_commit() {
    asm volatile("cp.async.commit_group;" ::: "memory");
}
template <int N>
__device__ __forceinline__ void cp_wait() {
    asm volatile("cp.async.wait_group %0;" :: "n"(N) : "memory");
}
__device__ __forceinline__ void ldsm_x4(uint32_t* r, uint32_t addr) {
    asm volatile("ldmatrix.sync.aligned.m8n8.x4.shared.b16 {%0,%1,%2,%3}, [%4];"
                 : "=r"(r[0]), "=r"(r[1]), "=r"(r[2]), "=r"(r[3]) : "r"(addr));
}
__device__ __forceinline__ void mma16816(float* d, const uint32_t* a, const uint32_t* b) {
    asm volatile(
        "mma.sync.aligned.m16n8k16.row.col.f32.bf16.bf16.f32 "
        "{%0,%1,%2,%3}, {%4,%5,%6,%7}, {%8,%9}, {%0,%1,%2,%3};"
        : "+f"(d[0]), "+f"(d[1]), "+f"(d[2]), "+f"(d[3])
        : "r"(a[0]), "r"(a[1]), "r"(a[2]), "r"(a[3]), "r"(b[0]), "r"(b[1]));
}
__device__ __forceinline__ unsigned short bf16_bits(float v) {
    return __bfloat16_as_ushort(__float2bfloat16(v));
}

// ---------------------------------------------------------------------------
__global__ void zero_kernel()
{
    const int i = blockIdx.x * 256 + threadIdx.x;
    if (i < NB * NHEADS * DHEAD * DHEAD) g_ctx[i] = 0.f;
    if (i < NB * NHEADS * DHEAD) g_ksum[i] = 0.f;
}

__global__ void conv_w_kernel(const float* __restrict__ wq)
{
    int i = blockIdx.x * 256 + threadIdx.x;
    float v = wq[i];
    __nv_bfloat16 hi = __float2bfloat16(v);
    ((__nv_bfloat16*)g_w_hi)[i] = hi;
    ((__nv_bfloat16*)g_w_lo)[i] = __float2bfloat16(v - __bfloat162float(hi));
}

__global__ __launch_bounds__(256) void conv_x_kernel(const float* __restrict__ x)
{
    __shared__ float s[32][129];
    const int bz = blockIdx.z;
    const int bi = bz >> 4, fi = bz & 15;
    const int n0 = blockIdx.x * 128;
    const int c0 = blockIdx.y * 32;
    const float* __restrict__ X = x + (size_t)bi * XB_STRIDE + (size_t)fi * NSP;
    const int tid = threadIdx.x;
#pragma unroll
    for (int it = 0; it < 16; it++) {
        int i = tid + it * 256;
        int c = i >> 7, n = i & 127;
        s[c][n] = X[(size_t)(c0 + c) * XC_STRIDE + n0 + n];
    }
    __syncthreads();
    __nv_bfloat16* ah = (__nv_bfloat16*)g_xt_hi;
    __nv_bfloat16* al = (__nv_bfloat16*)g_xt_lo;
#pragma unroll
    for (int it = 0; it < 16; it++) {
        int i = tid + it * 256;
        int n = i >> 5, c = i & 31;
        float v = s[c][n];
        __nv_bfloat16 hi = __float2bfloat16(v);
        size_t o = ((size_t)bz * NSP + n0 + n) * CDIM + c0 + c;
        ah[o] = hi;
        al[o] = __float2bfloat16(v - __bfloat162float(hi));
    }
}

// ---------------------------------------------------------------------------
// GEMM: CTA M128 x N128, K=256 (4 chunks of 64), 256 threads = 8 warps (2x4),
// warp tile 64x32 (4x4 m16n8k16). 3-stage cp.async + ks fragment pipelining.
// ---------------------------------------------------------------------------
#define BUF_BYTES 73728
#define OFF_AH 0
#define OFF_AL 18432
#define OFF_BH 36864
#define OFF_BL 55296

template <int MODE>
__global__ __launch_bounds__(256, 1) void gemm_mma_kernel(float* __restrict__ out,
                                                          const float* __restrict__ bias)
{
    extern __shared__ char smem[];
    const uint32_t sbase = smem_u32(smem);
    const int tid = threadIdx.x;
    const int lane = tid & 31;
    const int wid = tid >> 5;
    const int wm = wid >> 2;          // 0..1
    const int wn = wid & 3;           // 0..3
    const int bz = blockIdx.z;
    const int m0 = blockIdx.y * 128;
    const int n0 = blockIdx.x * 128;

    const uint4* __restrict__ Ah;
    const uint4* __restrict__ Al;
    if (MODE == 0) { Ah = g_w_hi; Al = g_w_lo; }
    else { Ah = g_w2_hi + (size_t)bz * 8192; Al = g_w2_lo + (size_t)bz * 8192; }
    const uint4* __restrict__ Bh = (MODE == 0 ? g_xt_hi : g_qsm_hi) + (size_t)bz * NSP * CDIM / 8;
    const uint4* __restrict__ Bl = (MODE == 0 ? g_xt_lo : g_qsm_lo) + (size_t)bz * NSP * CDIM / 8;

    float acc[4][4][4];
#pragma unroll
    for (int i = 0; i < 4; i++)
#pragma unroll
        for (int j = 0; j < 4; j++)
#pragma unroll
            for (int k = 0; k < 4; k++) acc[i][j][k] = 0.f;

    auto issue = [&](int kc, int buf) {
        const uint32_t bo = sbase + buf * BUF_BYTES;
#pragma unroll
        for (int i = tid; i < 1024; i += 256) {
            const int r = i >> 3, c = i & 7;
            const uint32_t so = (uint32_t)(r * 144 + c * 16);
            const size_t gA = (size_t)(m0 + r) * 32 + kc * 8 + c;
            const size_t gB = (size_t)(n0 + r) * 32 + kc * 8 + c;
            cp16(bo + OFF_AH + so, Ah + gA);
            cp16(bo + OFF_AL + so, Al + gA);
            cp16(bo + OFF_BH + so, Bh + gB);
            cp16(bo + OFF_BL + so, Bl + gB);
        }
    };

    issue(0, 0); cp_commit();
    issue(1, 1); cp_commit();

    const int arow = wm * 64 + (lane & 15);
    const int acsel = (lane >> 4) << 3;
    const int brow = wn * 32 + (lane & 7) + ((lane >> 4) & 1) * 8;   // + p*16
    const int bcsel = ((lane >> 3) & 1) << 3;

    // double-buffered register fragments across ks
    uint32_t ah[2][4][4], al[2][4][4], bh[2][2][4], bl[2][2][4];

    for (int kc = 0; kc < 4; kc++) {
        if (kc == 3) cp_wait<0>(); else cp_wait<1>();
        __syncthreads();

        const uint32_t bo = sbase + (kc % 3) * BUF_BYTES;

        // preload ks=0 fragments
#pragma unroll
        for (int mt = 0; mt < 4; mt++) {
            const uint32_t ao = bo + (uint32_t)((arow + mt * 16) * 144 + acsel * 2);
            ldsm_x4(ah[0][mt], ao + OFF_AH);
            ldsm_x4(al[0][mt], ao + OFF_AL);
        }
#pragma unroll
        for (int p = 0; p < 2; p++) {
            const uint32_t bo2 = bo + (uint32_t)((brow + p * 16) * 144 + bcsel * 2);
            ldsm_x4(bh[0][p], bo2 + OFF_BH);
            ldsm_x4(bl[0][p], bo2 + OFF_BL);
        }

#pragma unroll
        for (int ks = 0; ks < 4; ks++) {
            const int cur = ks & 1;
            const int nxt = cur ^ 1;
            if (ks < 3) {
                const int k0 = (ks + 1) * 16;
#pragma unroll
                for (int mt = 0; mt < 4; mt++) {
                    const uint32_t ao = bo + (uint32_t)((arow + mt * 16) * 144 + (k0 + acsel) * 2);
                    ldsm_x4(ah[nxt][mt], ao + OFF_AH);
                    ldsm_x4(al[nxt][mt], ao + OFF_AL);
                }
#pragma unroll
                for (int p = 0; p < 2; p++) {
                    const uint32_t bo2 = bo + (uint32_t)((brow + p * 16) * 144 + (k0 + bcsel) * 2);
                    ldsm_x4(bh[nxt][p], bo2 + OFF_BH);
                    ldsm_x4(bl[nxt][p], bo2 + OFF_BL);
                }
            }
#pragma unroll
            for (int mt = 0; mt < 4; mt++)
#pragma unroll
                for (int nt = 0; nt < 4; nt++) {
                    const int p = nt >> 1, sub = (nt & 1) * 2;
                    mma16816(acc[mt][nt], ah[cur][mt], bh[cur][p] + sub);
                    mma16816(acc[mt][nt], ah[cur][mt], bl[cur][p] + sub);
                    mma16816(acc[mt][nt], al[cur][mt], bh[cur][p] + sub);
                }
        }
        __syncthreads();
        if (kc + 2 < 4) { issue(kc + 2, (kc + 2) % 3); cp_commit(); }
    }

    // ------------- epilogue -------------
    if (MODE == 0 && m0 < 256) {
        // fused q-softmax: stage 128x128 fp32 tile (stride 132), softmax over d
        float* s = (float*)smem;
#pragma unroll
        for (int mt = 0; mt < 4; mt++) {
            const int r0 = wm * 64 + mt * 16 + (lane >> 2);
            const int c = wn * 32 + (lane & 3) * 2;
#pragma unroll
            for (int nt = 0; nt < 4; nt++) {
                *(float2*)&s[(size_t)r0 * 132 + c + nt * 8] =
                    make_float2(acc[mt][nt][0], acc[mt][nt][1]);
                *(float2*)&s[(size_t)(r0 + 8) * 132 + c + nt * 8] =
                    make_float2(acc[mt][nt][2], acc[mt][nt][3]);
            }
        }
        __syncthreads();
#pragma unroll
        for (int half = 0; half < 2; half++) {
            const int h = (tid >> 7) + half * 2;   // 0..3 local head
            const int n = tid & 127;
            float qv[32];
            float m = -3.0e38f;
#pragma unroll
            for (int d = 0; d < 32; d++) {
                qv[d] = s[(size_t)(h * 32 + d) * 132 + n];
                m = fmaxf(m, qv[d]);
            }
            float sum = 0.f;
#pragma unroll
            for (int d = 0; d < 32; d++) {
                qv[d] = __expf(qv[d] - m);
                sum += qv[d];
            }
            const float rs = 1.0f / sum;
            const size_t base = ((size_t)bz * NSP + n0 + n) * CDIM + m0 + h * 32;
            uint4* oh = g_qsm_hi + (base >> 3);
            uint4* ol = g_qsm_lo + (base >> 3);
#pragma unroll
            for (int g = 0; g < 4; g++) {
                uint32_t hw[4], lw[4];
#pragma unroll
                for (int p = 0; p < 4; p++) {
                    const float v0 = qv[g * 8 + p * 2] * rs;
                    const float v1 = qv[g * 8 + p * 2 + 1] * rs;
                    const unsigned short h0 = bf16_bits(v0);
                    const unsigned short h1 = bf16_bits(v1);
                    const float r0 = v0 - __bfloat162float(__ushort_as_bfloat16(h0));
                    const float r1 = v1 - __bfloat162float(__ushort_as_bfloat16(h1));
                    hw[p] = (uint32_t)h0 | ((uint32_t)h1 << 16);
                    lw[p] = (uint32_t)bf16_bits(r0) | ((uint32_t)bf16_bits(r1) << 16);
                }
                oh[g] = make_uint4(hw[0], hw[1], hw[2], hw[3]);
                ol[g] = make_uint4(lw[0], lw[1], lw[2], lw[3]);
            }
        }
    } else if (MODE == 0) {
        const int rbase = m0 - 256 + wm * 64 + (lane >> 2);
        const int cbase = n0 + wn * 32 + (lane & 3) * 2;
        float* __restrict__ O = g_kv + (size_t)bz * 512 * NSP;
#pragma unroll
        for (int mt = 0; mt < 4; mt++) {
#pragma unroll
            for (int nt = 0; nt < 4; nt++) {
                const int c = cbase + nt * 8;
                float* p0 = O + (size_t)(rbase + mt * 16) * NSP + c;
                float* p1 = O + (size_t)(rbase + mt * 16 + 8) * NSP + c;
                *(float2*)p0 = make_float2(acc[mt][nt][0], acc[mt][nt][1]);
                *(float2*)p1 = make_float2(acc[mt][nt][2], acc[mt][nt][3]);
            }
        }
    } else {
        const int rbase = m0 + wm * 64 + (lane >> 2);
        const int cbase = n0 + wn * 32 + (lane & 3) * 2;
        const int bi = bz >> 4, fi = bz & 15;
        float* __restrict__ O = out + (size_t)bi * XB_STRIDE + (size_t)fi * NSP;
#pragma unroll
        for (int mt = 0; mt < 4; mt++) {
            const int r0 = rbase + mt * 16;
            const float b0 = bias[r0];
            const float b1 = bias[r0 + 8];
#pragma unroll
            for (int nt = 0; nt < 4; nt++) {
                const int c = cbase + nt * 8;
                float* p0 = O + (size_t)r0 * XC_STRIDE + c;
                float* p1 = O + (size_t)(r0 + 8) * XC_STRIDE + c;
                *(float2*)p0 = make_float2(acc[mt][nt][0] + b0, acc[mt][nt][1] + b0);
                *(float2*)p1 = make_float2(acc[mt][nt][2] + b1, acc[mt][nt][3] + b1);
            }
        }
    }
}

// ---------------------------------------------------------------------------
// ctx partials + ksum: grid (16 chunks of 256 n, 256 bh). Unshifted exp(k).
// ---------------------------------------------------------------------------
__global__ __launch_bounds__(256) void ctx_kernel()
{
    __shared__ float ks[32][260];
    __shared__ float vs[32][260];
    const int bh = blockIdx.y;
    const int n0 = blockIdx.x * 256;
    const float* __restrict__ kp =
        g_kv + (size_t)(bh >> 3) * 512 * NSP + (size_t)((bh & 7) * DHEAD) * NSP;
    const float* __restrict__ vp = kp + (size_t)256 * NSP;
    const int tid = threadIdx.x;
    const int lane = tid & 31;
    const int warp = tid >> 5;

#pragma unroll
    for (int it = 0; it < 8; it++) {
        const int i = tid + it * 256;
        const int d = i >> 6, j4 = (i & 63) * 4;
        float4 kv = *(const float4*)(kp + (size_t)d * NSP + n0 + j4);
        ks[d][j4 + 0] = __expf(kv.x);
        ks[d][j4 + 1] = __expf(kv.y);
        ks[d][j4 + 2] = __expf(kv.z);
        ks[d][j4 + 3] = __expf(kv.w);
        *(float4*)&vs[d][j4] = *(const float4*)(vp + (size_t)d * NSP + n0 + j4);
    }
    __syncthreads();

    float acc[4] = {0.f, 0.f, 0.f, 0.f};
    const int w4 = warp * 4;
#pragma unroll
    for (int j = 0; j < 256; j += 4) {
        const float4 vv4 = *(const float4*)&vs[lane][j];
#pragma unroll
        for (int dd = 0; dd < 4; dd++) {
            const float4 kk4 = *(const float4*)&ks[w4 + dd][j];
            acc[dd] += kk4.x * vv4.x + kk4.y * vv4.y + kk4.z * vv4.z + kk4.w * vv4.w;
        }
    }
#pragma unroll
    for (int dd = 0; dd < 4; dd++) {
        float s = 0.f;
#pragma unroll
        for (int j = lane; j < 256; j += 32) s += ks[w4 + dd][j];
#pragma unroll
        for (int off = 16; off; off >>= 1) s += __shfl_xor_sync(0xffffffffu, s, off);
        if (lane == 0) atomicAdd(&g_ksum[bh * 32 + w4 + dd], s);
        atomicAdd(&g_ctx[bh * 1024 + (w4 + dd) * 32 + lane], acc[dd]);
    }
}

// ---------------------------------------------------------------------------
// W2[b][o][h*32+d] = scale/ksum[b,h,d] * sum_e w_out[o][h*32+e] * ctx[b,h,d,e]
// ---------------------------------------------------------------------------
__global__ __launch_bounds__(256) void w2_kernel(const float* __restrict__ w_out)
{
    __shared__ float wblk[256][33];
    __shared__ float cblk[32][33];
    __shared__ float rcp[32];
    const int b = blockIdx.x;
    const int tid = threadIdx.x;
    const float scale = 0.1767766953f;

    __nv_bfloat16* W2h = (__nv_bfloat16*)(g_w2_hi + (size_t)b * 8192);
    __nv_bfloat16* W2l = (__nv_bfloat16*)(g_w2_lo + (size_t)b * 8192);

    for (int h = 0; h < NHEADS; h++) {
#pragma unroll
        for (int i = tid; i < 8192; i += 256) {
            const int o = i >> 5, e = i & 31;
            wblk[o][e] = w_out[o * 256 + h * 32 + e];
        }
#pragma unroll
        for (int i = tid; i < 1024; i += 256)
            cblk[i >> 5][i & 31] = g_ctx[(b * 8 + h) * 1024 + i];
        if (tid < 32) rcp[tid] = scale / g_ksum[(b * 8 + h) * 32 + tid];
        __syncthreads();

        const int o = tid;
        float res[32];
#pragma unroll
        for (int d = 0; d < 32; d++) {
            float a = 0.f;
#pragma unroll
            for (int e = 0; e < 32; e++) a += wblk[o][e] * cblk[d][e];
            res[d] = a * rcp[d];
        }
#pragma unroll
        for (int d = 0; d < 32; d++) {
            const int c = h * 32 + d;
            __nv_bfloat16 hi = __float2bfloat16(res[d]);
            W2h[o * 256 + c] = hi;
            W2l[o * 256 + c] = __float2bfloat16(res[d] - __bfloat162float(hi));
        }
        __syncthreads();
    }
}

// ---------------------------------------------------------------------------
extern "C" void kernel_launch(void* const* d_in, const int* in_sizes, int n_in,
                              void* d_out, int out_size)
{
    (void)in_sizes; (void)n_in; (void)out_size;
    const float* x     = (const float*)d_in[0];
    const float* w_qkv = (const float*)d_in[1];
    const float* w_out = (const float*)d_in[2];
    const float* b_out = (const float*)d_in[3];
    float* out = (float*)d_out;

    const int SMEM = 3 * BUF_BYTES;   // 221184
    cudaFuncSetAttribute(gemm_mma_kernel<0>, cudaFuncAttributeMaxDynamicSharedMemorySize, SMEM);
    cudaFuncSetAttribute(gemm_mma_kernel<1>, cudaFuncAttributeMaxDynamicSharedMemorySize, SMEM);

    zero_kernel<<<1056, 256>>>();
    conv_w_kernel<<<768, 256>>>(w_qkv);
    conv_x_kernel<<<dim3(NSP / 128, CDIM / 32, NB), 256>>>(x);
    gemm_mma_kernel<0><<<dim3(NSP / 128, O3 / 128, NB), 256, SMEM>>>(nullptr, nullptr);
    ctx_kernel<<<dim3(16, NB * NHEADS), 256>>>();
    w2_kernel<<<NB, 256>>>(w_out);
    gemm_mma_kernel<1><<<dim3(NSP / 128, CDIM / 128, NB), 256, SMEM>>>(out, b_out);
}

// round 14
// speedup vs baseline: 1.6433x; 1.0433x over previous
#include <cuda_runtime.h>
#include <cuda_bf16.h>
#include <cstdint>

// ---------------------------------------------------------------------------
// SpatialLinearAttention — mma.sync split-bf16, W2 fusion, fused q-softmax
//   GEMM CTA 128x256, 8 warps, warp tile 64x64, 2-stage cp.async pipeline.
// ---------------------------------------------------------------------------

#define NB      32
#define CDIM    256
#define NSP     4096
#define O3      768
#define NHEADS  8
#define DHEAD   32
#define XB_STRIDE (CDIM * 16 * NSP)
#define XC_STRIDE (16 * NSP)

// ---------------- scratch ---------------------------------------------------
__device__ float g_kv[(size_t)NB * 512 * NSP];           // k rows 0-255, v 256-511
__device__ uint4 g_w_hi[24576];                          // 768 x 256 bf16
__device__ uint4 g_w_lo[24576];
__device__ uint4 g_xt_hi[4194304];                       // [b][n][c] bf16
__device__ uint4 g_xt_lo[4194304];
__device__ uint4 g_qsm_hi[4194304];                      // [b][n][c] bf16
__device__ uint4 g_qsm_lo[4194304];
__device__ uint4 g_w2_hi[262144];                        // [b] 256x256 bf16
__device__ uint4 g_w2_lo[262144];
__device__ float g_ctx[NB * NHEADS * DHEAD * DHEAD];     // sum exp(k)*v
__device__ float g_ksum[NB * NHEADS * DHEAD];

// ---------------- helpers ---------------------------------------------------
__device__ __forceinline__ uint32_t smem_u32(const void* p) {
    uint32_t a;
    asm("{ .reg .u64 t; cvta.to.shared.u64 t, %1; cvt.u32.u64 %0, t; }" : "=r"(a) : "l"(p));
    return a;
}
__device__ __forceinline__ void cp16(uint32_t saddr, const void* g) {
    asm volatile("cp.async.ca.shared.global [%0], [%1], 16;" :: "r"(saddr), "l"(g) : "memory");
}
__device__ __forceinline__ void cp_commit() {
    asm volatile("cp.async.commit_group;" ::: "memory");
}
template <int N>
__device__ __forceinline__ void cp_wait() {
    asm volatile("cp.async.wait_group %0;" :: "n"(N) : "memory");
}
__device__ __forceinline__ void ldsm_x4(uint32_t* r, uint32_t addr) {
    asm volatile("ldmatrix.sync.aligned.m8n8.x4.shared.b16 {%0,%1,%2,%3}, [%4];"
                 : "=r"(r[0]), "=r"(r[1]), "=r"(r[2]), "=r"(r[3]) : "r"(addr));
}
__device__ __forceinline__ void mma16816(float* d, const uint32_t* a, const uint32_t* b) {
    asm volatile(
        "mma.sync.aligned.m16n8k16.row.col.f32.bf16.bf16.f32 "
        "{%0,%1,%2,%3}, {%4,%5,%6,%7}, {%8,%9}, {%0,%1,%2,%3};"
        : "+f"(d[0]), "+f"(d[1]), "+f"(d[2]), "+f"(d[3])
        : "r"(a[0]), "r"(a[1]), "r"(a[2]), "r"(a[3]), "r"(b[0]), "r"(b[1]));
}
__device__ __forceinline__ unsigned short bf16_bits(float v) {
    return __bfloat16_as_ushort(__float2bfloat16(v));
}

// ---------------------------------------------------------------------------
__global__ void zero_kernel()
{
    const int i = blockIdx.x * 256 + threadIdx.x;
    if (i < NB * NHEADS * DHEAD * DHEAD) g_ctx[i] = 0.f;
    if (i < NB * NHEADS * DHEAD) g_ksum[i] = 0.f;
}

__global__ void conv_w_kernel(const float* __restrict__ wq)
{
    int i = blockIdx.x * 256 + threadIdx.x;
    float v = wq[i];
    __nv_bfloat16 hi = __float2bfloat16(v);
    ((__nv_bfloat16*)g_w_hi)[i] = hi;
    ((__nv_bfloat16*)g_w_lo)[i] = __float2bfloat16(v - __bfloat162float(hi));
}

__global__ __launch_bounds__(256) void conv_x_kernel(const float* __restrict__ x)
{
    __shared__ float s[32][129];
    const int bz = blockIdx.z;
    const int bi = bz >> 4, fi = bz & 15;
    const int n0 = blockIdx.x * 128;
    const int c0 = blockIdx.y * 32;
    const float* __restrict__ X = x + (size_t)bi * XB_STRIDE + (size_t)fi * NSP;
    const int tid = threadIdx.x;
#pragma unroll
    for (int it = 0; it < 16; it++) {
        int i = tid + it * 256;
        int c = i >> 7, n = i & 127;
        s[c][n] = X[(size_t)(c0 + c) * XC_STRIDE + n0 + n];
    }
    __syncthreads();
    __nv_bfloat16* ah = (__nv_bfloat16*)g_xt_hi;
    __nv_bfloat16* al = (__nv_bfloat16*)g_xt_lo;
#pragma unroll
    for (int it = 0; it < 16; it++) {
        int i = tid + it * 256;
        int n = i >> 5, c = i & 31;
        float v = s[c][n];
        __nv_bfloat16 hi = __float2bfloat16(v);
        size_t o = ((size_t)bz * NSP + n0 + n) * CDIM + c0 + c;
        ah[o] = hi;
        al[o] = __float2bfloat16(v - __bfloat162float(hi));
    }
}

// ---------------------------------------------------------------------------
// GEMM: CTA M128 x N256, K=256 (4 chunks of 64), 256 threads = 8 warps (2x4),
// warp tile 64x64 (4x8 m16n8k16), 2-stage cp.async pipeline.
// ---------------------------------------------------------------------------
#define BUF_BYTES 110592       // A(hi+lo) 2*18432 + B(hi+lo) 2*36864
#define OFF_AH 0
#define OFF_AL 18432
#define OFF_BH 36864
#define OFF_BL 73728

template <int MODE>
__global__ __launch_bounds__(256, 1) void gemm_mma_kernel(float* __restrict__ out,
                                                          const float* __restrict__ bias)
{
    extern __shared__ char smem[];
    const uint32_t sbase = smem_u32(smem);
    const int tid = threadIdx.x;
    const int lane = tid & 31;
    const int wid = tid >> 5;
    const int wm = wid >> 2;          // 0..1  (64 M each)
    const int wn = wid & 3;           // 0..3  (64 N each)
    const int bz = blockIdx.z;
    const int m0 = blockIdx.y * 128;
    const int n0 = blockIdx.x * 256;

    const uint4* __restrict__ Ah;
    const uint4* __restrict__ Al;
    if (MODE == 0) { Ah = g_w_hi; Al = g_w_lo; }
    else { Ah = g_w2_hi + (size_t)bz * 8192; Al = g_w2_lo + (size_t)bz * 8192; }
    const uint4* __restrict__ Bh = (MODE == 0 ? g_xt_hi : g_qsm_hi) + (size_t)bz * NSP * CDIM / 8;
    const uint4* __restrict__ Bl = (MODE == 0 ? g_xt_lo : g_qsm_lo) + (size_t)bz * NSP * CDIM / 8;

    float acc[4][8][4];
#pragma unroll
    for (int i = 0; i < 4; i++)
#pragma unroll
        for (int j = 0; j < 8; j++)
#pragma unroll
            for (int k = 0; k < 4; k++) acc[i][j][k] = 0.f;

    auto issue = [&](int kc, int buf) {
        const uint32_t bo = sbase + buf * BUF_BYTES;
#pragma unroll
        for (int i = tid; i < 1024; i += 256) {       // A: 128 rows x 8 u4
            const int r = i >> 3, c = i & 7;
            const uint32_t so = (uint32_t)(r * 144 + c * 16);
            const size_t gA = (size_t)(m0 + r) * 32 + kc * 8 + c;
            cp16(bo + OFF_AH + so, Ah + gA);
            cp16(bo + OFF_AL + so, Al + gA);
        }
#pragma unroll
        for (int i = tid; i < 2048; i += 256) {       // B: 256 rows x 8 u4
            const int r = i >> 3, c = i & 7;
            const uint32_t so = (uint32_t)(r * 144 + c * 16);
            const size_t gB = (size_t)(n0 + r) * 32 + kc * 8 + c;
            cp16(bo + OFF_BH + so, Bh + gB);
            cp16(bo + OFF_BL + so, Bl + gB);
        }
    };

    issue(0, 0);
    cp_commit();

    const int arow = wm * 64 + (lane & 15);
    const int acsel = (lane >> 4) << 3;
    const int brow = wn * 64 + (lane & 7) + ((lane >> 4) & 1) * 8;   // + p*16
    const int bcsel = ((lane >> 3) & 1) << 3;

    for (int kc = 0; kc < 4; kc++) {
        if (kc < 3) {
            issue(kc + 1, (kc + 1) & 1);
            cp_commit();
            cp_wait<1>();
        } else {
            cp_wait<0>();
        }
        __syncthreads();

        const uint32_t bo = sbase + (kc & 1) * BUF_BYTES;
#pragma unroll
        for (int ks = 0; ks < 4; ks++) {
            const int k0 = ks * 16;
            uint32_t ah[4][4], al[4][4];
#pragma unroll
            for (int mt = 0; mt < 4; mt++) {
                const uint32_t ao = bo + (uint32_t)((arow + mt * 16) * 144 + (k0 + acsel) * 2);
                ldsm_x4(ah[mt], ao + OFF_AH);
                ldsm_x4(al[mt], ao + OFF_AL);
            }
#pragma unroll
            for (int p = 0; p < 4; p++) {
                uint32_t bh[4], bl[4];
                const uint32_t bo2 = bo + (uint32_t)((brow + p * 16) * 144 + (k0 + bcsel) * 2);
                ldsm_x4(bh, bo2 + OFF_BH);
                ldsm_x4(bl, bo2 + OFF_BL);
#pragma unroll
                for (int mt = 0; mt < 4; mt++)
#pragma unroll
                    for (int q = 0; q < 2; q++) {
                        const int nt = p * 2 + q;
                        mma16816(acc[mt][nt], ah[mt], bh + q * 2);
                        mma16816(acc[mt][nt], ah[mt], bl + q * 2);
                        mma16816(acc[mt][nt], al[mt], bh + q * 2);
                    }
            }
        }
        __syncthreads();
    }

    // ------------- epilogue -------------
    if (MODE == 0 && m0 < 256) {
        // fused q-softmax: stage 128x256 fp32 tile (stride 260), softmax over d
        float* s = (float*)smem;
#pragma unroll
        for (int mt = 0; mt < 4; mt++) {
            const int r0 = wm * 64 + mt * 16 + (lane >> 2);
            const int c = wn * 64 + (lane & 3) * 2;
#pragma unroll
            for (int nt = 0; nt < 8; nt++) {
                *(float2*)&s[(size_t)r0 * 260 + c + nt * 8] =
                    make_float2(acc[mt][nt][0], acc[mt][nt][1]);
                *(float2*)&s[(size_t)(r0 + 8) * 260 + c + nt * 8] =
                    make_float2(acc[mt][nt][2], acc[mt][nt][3]);
            }
        }
        __syncthreads();
#pragma unroll
        for (int rep = 0; rep < 4; rep++) {
            const int task = rep * 256 + tid;     // 1024 tasks
            const int h = task >> 8;              // 0..3 local head
            const int n = task & 255;
            float qv[32];
            float m = -3.0e38f;
#pragma unroll
            for (int d = 0; d < 32; d++) {
                qv[d] = s[(size_t)(h * 32 + d) * 260 + n];
                m = fmaxf(m, qv[d]);
            }
            float sum = 0.f;
#pragma unroll
            for (int d = 0; d < 32; d++) {
                qv[d] = __expf(qv[d] - m);
                sum += qv[d];
            }
            const float rs = 1.0f / sum;
            const size_t base = ((size_t)bz * NSP + n0 + n) * CDIM + m0 + h * 32;
            uint4* oh = g_qsm_hi + (base >> 3);
            uint4* ol = g_qsm_lo + (base >> 3);
#pragma unroll
            for (int g = 0; g < 4; g++) {
                uint32_t hw[4], lw[4];
#pragma unroll
                for (int p = 0; p < 4; p++) {
                    const float v0 = qv[g * 8 + p * 2] * rs;
                    const float v1 = qv[g * 8 + p * 2 + 1] * rs;
                    const unsigned short h0 = bf16_bits(v0);
                    const unsigned short h1 = bf16_bits(v1);
                    const float r0 = v0 - __bfloat162float(__ushort_as_bfloat16(h0));
                    const float r1 = v1 - __bfloat162float(__ushort_as_bfloat16(h1));
                    hw[p] = (uint32_t)h0 | ((uint32_t)h1 << 16);
                    lw[p] = (uint32_t)bf16_bits(r0) | ((uint32_t)bf16_bits(r1) << 16);
                }
                oh[g] = make_uint4(hw[0], hw[1], hw[2], hw[3]);
                ol[g] = make_uint4(lw[0], lw[1], lw[2], lw[3]);
            }
        }
    } else if (MODE == 0) {
        const int rbase = m0 - 256 + wm * 64 + (lane >> 2);
        const int cbase = n0 + wn * 64 + (lane & 3) * 2;
        float* __restrict__ O = g_kv + (size_t)bz * 512 * NSP;
#pragma unroll
        for (int mt = 0; mt < 4; mt++) {
#pragma unroll
            for (int nt = 0; nt < 8; nt++) {
                const int c = cbase + nt * 8;
                float* p0 = O + (size_t)(rbase + mt * 16) * NSP + c;
                float* p1 = O + (size_t)(rbase + mt * 16 + 8) * NSP + c;
                *(float2*)p0 = make_float2(acc[mt][nt][0], acc[mt][nt][1]);
                *(float2*)p1 = make_float2(acc[mt][nt][2], acc[mt][nt][3]);
            }
        }
    } else {
        const int rbase = m0 + wm * 64 + (lane >> 2);
        const int cbase = n0 + wn * 64 + (lane & 3) * 2;
        const int bi = bz >> 4, fi = bz & 15;
        float* __restrict__ O = out + (size_t)bi * XB_STRIDE + (size_t)fi * NSP;
#pragma unroll
        for (int mt = 0; mt < 4; mt++) {
            const int r0 = rbase + mt * 16;
            const float b0 = bias[r0];
            const float b1 = bias[r0 + 8];
#pragma unroll
            for (int nt = 0; nt < 8; nt++) {
                const int c = cbase + nt * 8;
                float* p0 = O + (size_t)r0 * XC_STRIDE + c;
                float* p1 = O + (size_t)(r0 + 8) * XC_STRIDE + c;
                *(float2*)p0 = make_float2(acc[mt][nt][0] + b0, acc[mt][nt][1] + b0);
                *(float2*)p1 = make_float2(acc[mt][nt][2] + b1, acc[mt][nt][3] + b1);
            }
        }
    }
}

// ---------------------------------------------------------------------------
// ctx partials + ksum: grid (16 chunks of 256 n, 256 bh). Unshifted exp(k).
// ---------------------------------------------------------------------------
__global__ __launch_bounds__(256) void ctx_kernel()
{
    __shared__ float ks[32][260];
    __shared__ float vs[32][260];
    const int bh = blockIdx.y;
    const int n0 = blockIdx.x * 256;
    const float* __restrict__ kp =
        g_kv + (size_t)(bh >> 3) * 512 * NSP + (size_t)((bh & 7) * DHEAD) * NSP;
    const float* __restrict__ vp = kp + (size_t)256 * NSP;
    const int tid = threadIdx.x;
    const int lane = tid & 31;
    const int warp = tid >> 5;

#pragma unroll
    for (int it = 0; it < 8; it++) {
        const int i = tid + it * 256;
        const int d = i >> 6, j4 = (i & 63) * 4;
        float4 kv = *(const float4*)(kp + (size_t)d * NSP + n0 + j4);
        ks[d][j4 + 0] = __expf(kv.x);
        ks[d][j4 + 1] = __expf(kv.y);
        ks[d][j4 + 2] = __expf(kv.z);
        ks[d][j4 + 3] = __expf(kv.w);
        *(float4*)&vs[d][j4] = *(const float4*)(vp + (size_t)d * NSP + n0 + j4);
    }
    __syncthreads();

    float acc[4] = {0.f, 0.f, 0.f, 0.f};
    const int w4 = warp * 4;
#pragma unroll
    for (int j = 0; j < 256; j += 4) {
        const float4 vv4 = *(const float4*)&vs[lane][j];
#pragma unroll
        for (int dd = 0; dd < 4; dd++) {
            const float4 kk4 = *(const float4*)&ks[w4 + dd][j];
            acc[dd] += kk4.x * vv4.x + kk4.y * vv4.y + kk4.z * vv4.z + kk4.w * vv4.w;
        }
    }
#pragma unroll
    for (int dd = 0; dd < 4; dd++) {
        float s = 0.f;
#pragma unroll
        for (int j = lane; j < 256; j += 32) s += ks[w4 + dd][j];
#pragma unroll
        for (int off = 16; off; off >>= 1) s += __shfl_xor_sync(0xffffffffu, s, off);
        if (lane == 0) atomicAdd(&g_ksum[bh * 32 + w4 + dd], s);
        atomicAdd(&g_ctx[bh * 1024 + (w4 + dd) * 32 + lane], acc[dd]);
    }
}

// ---------------------------------------------------------------------------
// W2[b][o][h*32+d] = scale/ksum[b,h,d] * sum_e w_out[o][h*32+e] * ctx[b,h,d,e]
// ---------------------------------------------------------------------------
__global__ __launch_bounds__(256) void w2_kernel(const float* __restrict__ w_out)
{
    __shared__ float wblk[256][33];
    __shared__ float cblk[32][33];
    __shared__ float rcp[32];
    const int b = blockIdx.x;
    const int tid = threadIdx.x;
    const float scale = 0.1767766953f;

    __nv_bfloat16* W2h = (__nv_bfloat16*)(g_w2_hi + (size_t)b * 8192);
    __nv_bfloat16* W2l = (__nv_bfloat16*)(g_w2_lo + (size_t)b * 8192);

    for (int h = 0; h < NHEADS; h++) {
#pragma unroll
        for (int i = tid; i < 8192; i += 256) {
            const int o = i >> 5, e = i & 31;
            wblk[o][e] = w_out[o * 256 + h * 32 + e];
        }
#pragma unroll
        for (int i = tid; i < 1024; i += 256)
            cblk[i >> 5][i & 31] = g_ctx[(b * 8 + h) * 1024 + i];
        if (tid < 32) rcp[tid] = scale / g_ksum[(b * 8 + h) * 32 + tid];
        __syncthreads();

        const int o = tid;
        float res[32];
#pragma unroll
        for (int d = 0; d < 32; d++) {
            float a = 0.f;
#pragma unroll
            for (int e = 0; e < 32; e++) a += wblk[o][e] * cblk[d][e];
            res[d] = a * rcp[d];
        }
#pragma unroll
        for (int d = 0; d < 32; d++) {
            const int c = h * 32 + d;
            __nv_bfloat16 hi = __float2bfloat16(res[d]);
            W2h[o * 256 + c] = hi;
            W2l[o * 256 + c] = __float2bfloat16(res[d] - __bfloat162float(hi));
        }
        __syncthreads();
    }
}

// ---------------------------------------------------------------------------
extern "C" void kernel_launch(void* const* d_in, const int* in_sizes, int n_in,
                              void* d_out, int out_size)
{
    (void)in_sizes; (void)n_in; (void)out_size;
    const float* x     = (const float*)d_in[0];
    const float* w_qkv = (const float*)d_in[1];
    const float* w_out = (const float*)d_in[2];
    const float* b_out = (const float*)d_in[3];
    float* out = (float*)d_out;

    const int SMEM = 2 * BUF_BYTES;   // 221184
    cudaFuncSetAttribute(gemm_mma_kernel<0>, cudaFuncAttributeMaxDynamicSharedMemorySize, SMEM);
    cudaFuncSetAttribute(gemm_mma_kernel<1>, cudaFuncAttributeMaxDynamicSharedMemorySize, SMEM);

    zero_kernel<<<1056, 256>>>();
    conv_w_kernel<<<768, 256>>>(w_qkv);
    conv_x_kernel<<<dim3(NSP / 128, CDIM / 32, NB), 256>>>(x);
    gemm_mma_kernel<0><<<dim3(NSP / 256, O3 / 128, NB), 256, SMEM>>>(nullptr, nullptr);
    ctx_kernel<<<dim3(16, NB * NHEADS), 256>>>();
    w2_kernel<<<NB, 256>>>(w_out);
    gemm_mma_kernel<1><<<dim3(NSP / 256, CDIM / 128, NB), 256, SMEM>>>(out, b_out);
}